// round 14
// baseline (speedup 1.0000x reference)
#include <cuda_runtime.h>
#include <cuda_fp16.h>
#include <cstdint>

// out[n,o] = sum_i x[n,i] * sign(W[o,i]) + b[o],  N=IN=OUT=4096, fp32 in/out.
//
// Legacy HMMA f32-acc mma.sync (tcgen05 not emittable at compute_103).
// Round-13 evidence: wave quantization is NOT the binding loss (SM-level
// work-steal + co-residency smooth it); the ~18% tensor idle is correlated
// per-tile prologue/epilogue drains. Round-14: persistent dual-tile CTAs —
// 512 CTAs, each runs tiles bid and bid+512 as ONE 128-ktile pipeline that
// flows through the tile boundary (tile1 prefetch during tile0 tail, mid-
// stream epilogue under in-flight loads). Structure otherwise = round 11:
// CTA 128x128, 4 warps 64x64, KTILE 64, 3-stage cp.async, barrier-crossing
// fragment carry, 2 CTAs/SM.

#define N_DIM 4096
constexpr int KTILE = 64;
constexpr int NKT = N_DIM / KTILE;           // 64 per tile
constexpr int GKT = 2 * NKT;                 // 128 global ktiles per CTA
constexpr int STAGE_BYTES = 2 * 128 * 128;   // A 16KB + B 16KB
constexpr int SMEM_BYTES = 3 * STAGE_BYTES;  // 98304
constexpr int GRID = 512;                    // each CTA: tiles bid, bid+512

__device__ __half g_xh[(size_t)N_DIM * N_DIM];
__device__ __half g_wb[(size_t)N_DIM * N_DIM];

// ---------------------------------------------------------------------------
// prep: binarize W -> fp16, cast x -> fp16
// ---------------------------------------------------------------------------
__global__ void prep_kernel(const float4* __restrict__ x,
                            const float4* __restrict__ W, int n4) {
    int i = blockIdx.x * blockDim.x + threadIdx.x;
    if (i >= n4) return;
    float4 xv = x[i];
    float4 wv = W[i];
    float xs[4] = {xv.x, xv.y, xv.z, xv.w};
    float ws[4] = {wv.x, wv.y, wv.z, wv.w};
    alignas(8) __half xh[4], wb[4];
#pragma unroll
    for (int j = 0; j < 4; j++) {
        xh[j] = __float2half_rn(xs[j]);
        float s = (ws[j] > 0.0f) ? 1.0f : ((ws[j] < 0.0f) ? -1.0f : 0.0f);
        wb[j] = __float2half_rn(s);
    }
    size_t base = (size_t)i * 4;
    *reinterpret_cast<uint2*>(g_xh + base) = *reinterpret_cast<uint2*>(xh);
    *reinterpret_cast<uint2*>(g_wb + base) = *reinterpret_cast<uint2*>(wb);
}

// ---------------------------------------------------------------------------
// PTX helpers
// ---------------------------------------------------------------------------
__device__ __forceinline__ void cp16(uint32_t smem_addr, const void* gmem_ptr) {
    asm volatile("cp.async.cg.shared.global [%0], [%1], 16;\n"
                 :: "r"(smem_addr), "l"(gmem_ptr) : "memory");
}

__device__ __forceinline__ void ldsm_x4(uint32_t* r, uint32_t a) {
    asm volatile("ldmatrix.sync.aligned.m8n8.x4.shared.b16 {%0,%1,%2,%3}, [%4];\n"
                 : "=r"(r[0]), "=r"(r[1]), "=r"(r[2]), "=r"(r[3]) : "r"(a));
}

__device__ __forceinline__ void mma16816(float* d, const uint32_t* a,
                                         const uint32_t* b) {
    asm volatile("mma.sync.aligned.m16n8k16.row.col.f32.f16.f16.f32 "
                 "{%0,%1,%2,%3},{%4,%5,%6,%7},{%8,%9},{%0,%1,%2,%3};\n"
                 : "+f"(d[0]), "+f"(d[1]), "+f"(d[2]), "+f"(d[3])
                 : "r"(a[0]), "r"(a[1]), "r"(a[2]), "r"(a[3]),
                   "r"(b[0]), "r"(b[1]));
}

// ---------------------------------------------------------------------------
// GEMM: 128 threads = 4 warps in 2(M) x 2(N), warp tile 64x64.
// Stage layout: A rows 0-127 (128B/row XOR-swizzled); B at +16384 same.
// Swizzle: byte_off(row, ch16) = row*128 + ((ch16 ^ (row&7)) << 4)
// ---------------------------------------------------------------------------
__global__ void __launch_bounds__(128, 2)
gemm_kernel(const float* __restrict__ bias, float* __restrict__ out) {
    extern __shared__ char smem[];
    const uint32_t smem_base = (uint32_t)__cvta_generic_to_shared(smem);
    const int tid   = threadIdx.x;
    const int lane  = tid & 31;
    const int warp  = tid >> 5;
    const int warpM = warp & 1;
    const int warpN = warp >> 1;

    // two tiles per CTA: t0 = bid, t1 = bid + 512 (same nT -> B reuse in L2)
    const int t0 = blockIdx.x;
    const int t1 = t0 + GRID;
    const int mBase0 = (t0 >> 5) * 128, nBase0 = (t0 & 31) * 128;
    const int mBase1 = (t1 >> 5) * 128, nBase1 = (t1 & 31) * 128;

    float acc[4][8][4];
#pragma unroll
    for (int a = 0; a < 4; a++)
#pragma unroll
        for (int b = 0; b < 8; b++)
#pragma unroll
            for (int c = 0; c < 4; c++) acc[a][b][c] = 0.0f;

    // ---- cp.async per-thread mapping: ch16 = tid&7, rows rbase + p*16 ----
    const int rbase = tid >> 3;               // 0..15
    const int ch    = tid & 7;
    const uint32_t swA = (uint32_t)rbase * 128 + (uint32_t)((ch ^ (rbase & 7)) << 4);
    const __half* gA0 = g_xh + (size_t)(mBase0 + rbase) * N_DIM + ch * 8;
    const __half* gB0 = g_wb + (size_t)(nBase0 + rbase) * N_DIM + ch * 8;
    const __half* gA1 = g_xh + (size_t)(mBase1 + rbase) * N_DIM + ch * 8;
    const __half* gB1 = g_wb + (size_t)(nBase1 + rbase) * N_DIM + ch * 8;

    // g = global ktile index 0..127; tile = g>>6, kt = g&63
    auto prefetch = [&](int g) {
        const uint32_t sb = smem_base + (uint32_t)(g % 3) * STAGE_BYTES;
        const int k0 = (g & 63) * KTILE;
        const __half* gA = (g < NKT) ? gA0 : gA1;
        const __half* gB = (g < NKT) ? gB0 : gB1;
#pragma unroll
        for (int p = 0; p < 8; p++) {
            uint32_t so = swA + (uint32_t)p * 2048;      // +16 rows
            size_t go = (size_t)p * 16 * N_DIM + k0;
            cp16(sb + so,         gA + go);
            cp16(sb + 16384 + so, gB + go);
        }
        asm volatile("cp.async.commit_group;\n" ::: "memory");
    };

    // ---- ldmatrix per-thread row/offset precompute ----
    const uint32_t la7 = lane & 7;
    const uint32_t aHi = (lane >> 4) & 1;     // k +8 selector for A
    const uint32_t bHi = (lane >> 3) & 1;     // k +8 selector for B
    uint32_t aOff[4], bOff[4];
#pragma unroll
    for (int tm = 0; tm < 4; tm++) {
        uint32_t r = warpM * 64 + tm * 16 + (lane & 15);
        aOff[tm] = r * 128;
    }
#pragma unroll
    for (int pr = 0; pr < 4; pr++) {
        uint32_t r = warpN * 64 + pr * 16 + la7 + ((lane >> 4) & 1) * 8;
        bOff[pr] = 16384 + r * 128;
    }

    uint32_t ah[2][4][4], bq[2][4][4];

    auto loadfrags = [&](uint32_t sb, int ks, int buf) {
        const uint32_t ca = (((uint32_t)ks * 2 + aHi) ^ la7) << 4;
        const uint32_t cb = (((uint32_t)ks * 2 + bHi) ^ la7) << 4;
#pragma unroll
        for (int tm = 0; tm < 4; tm++) ldsm_x4(ah[buf][tm], sb + aOff[tm] + ca);
#pragma unroll
        for (int pr = 0; pr < 4; pr++) ldsm_x4(bq[buf][pr], sb + bOff[pr] + cb);
    };

    auto mmas = [&](int buf) {
#pragma unroll
        for (int tm = 0; tm < 4; tm++)
#pragma unroll
            for (int pr = 0; pr < 4; pr++) {
                mma16816(acc[tm][2 * pr],     ah[buf][tm], &bq[buf][pr][0]);
                mma16816(acc[tm][2 * pr + 1], ah[buf][tm], &bq[buf][pr][2]);
            }
    };

    // epilogue for one tile: + bias, fp32 store, acc reset
    const int g_   = lane >> 2;
    const int t4   = lane & 3;
    auto epilogue = [&](int mBase, int nBase) {
#pragma unroll
        for (int tm = 0; tm < 4; tm++) {
            int rr = mBase + warpM * 64 + tm * 16 + g_;
#pragma unroll
            for (int tn = 0; tn < 8; tn++) {
                int col = nBase + warpN * 64 + tn * 8 + 2 * t4;
                float2 b2 = *reinterpret_cast<const float2*>(bias + col);
                float2 v0, v1;
                v0.x = acc[tm][tn][0] + b2.x;
                v0.y = acc[tm][tn][1] + b2.y;
                v1.x = acc[tm][tn][2] + b2.x;
                v1.y = acc[tm][tn][3] + b2.y;
                *reinterpret_cast<float2*>(out + (size_t)rr * N_DIM + col)       = v0;
                *reinterpret_cast<float2*>(out + (size_t)(rr + 8) * N_DIM + col) = v1;
                acc[tm][tn][0] = 0.0f; acc[tm][tn][1] = 0.0f;
                acc[tm][tn][2] = 0.0f; acc[tm][tn][3] = 0.0f;
            }
        }
    };

    prefetch(0);
    prefetch(1);
    asm volatile("cp.async.wait_group 1;\n" ::: "memory");
    __syncthreads();
    loadfrags(smem_base, 0, 0);   // (g=0, ks=0) into buf 0

    for (int g = 0; g < GKT; g++) {
        const uint32_t sb = smem_base + (uint32_t)(g % 3) * STAGE_BYTES;
#pragma unroll
        for (int ks = 0; ks < 3; ks++) {
            loadfrags(sb, ks + 1, (ks + 1) & 1);
            mmas(ks & 1);
        }
        // ks3 frags in buf 1, not yet crunched
        if (g + 2 < GKT) prefetch(g + 2);
        if (g + 1 < GKT) {
            if (g + 2 < GKT)
                asm volatile("cp.async.wait_group 1;\n" ::: "memory");
            else
                asm volatile("cp.async.wait_group 0;\n" ::: "memory");
            __syncthreads();
            loadfrags(smem_base + (uint32_t)((g + 1) % 3) * STAGE_BYTES, 0, 0);
        }
        mmas(1);   // keeps tensor pipe busy through the sync window
        if (g == NKT - 1)
            epilogue(mBase0, nBase0);   // mid-stream: tile1 loads already in flight
    }
    epilogue(mBase1, nBase1);
}

// ---------------------------------------------------------------------------
extern "C" void kernel_launch(void* const* d_in, const int* in_sizes, int n_in,
                              void* d_out, int out_size) {
    const float* x = (const float*)d_in[0];
    const float* W = (const float*)d_in[1];
    const float* b = (const float*)d_in[2];
    float* out = (float*)d_out;

    const int n4 = (N_DIM * N_DIM) / 4;
    prep_kernel<<<(n4 + 255) / 256, 256>>>((const float4*)x, (const float4*)W, n4);

    cudaFuncSetAttribute(gemm_kernel, cudaFuncAttributeMaxDynamicSharedMemorySize,
                         SMEM_BYTES);
    gemm_kernel<<<GRID, 128, SMEM_BYTES>>>(b, out);
}

// round 15
// speedup vs baseline: 1.1269x; 1.1269x over previous
#include <cuda_runtime.h>
#include <cuda_fp16.h>
#include <cstdint>

// out[n,o] = sum_i x[n,i] * sign(W[o,i]) + b[o],  N=IN=OUT=4096, fp32 in/out.
//
// Legacy HMMA f32-acc mma.sync (tcgen05 not emittable at compute_103).
// Round-11 (best): barrier-crossing fragment carry -> tensor 82.2%. Gap budget
// says per-ktile barrier skew is the largest remaining loss. Round-15: HALVE
// the barrier count. CTA 128x256 (256 thr, 8 warps 2Mx4N, warp tile 64x64),
// 4 stages of KTILE=64 (48KB each, 192KB smem, occ 1), ONE wait+syncthreads
// per 2-ktile window, prefetch of kt+2/kt+3 right after the window barrier,
// kt+1's ks3 MMAs carried across the barrier (round-11 trick).

#define N_DIM 4096
constexpr int KTILE = 64;
constexpr int NKT = N_DIM / KTILE;            // 64
constexpr int STAGE_BYTES = 16384 + 32768;    // A 16KB + B 32KB
constexpr int SMEM_BYTES = 4 * STAGE_BYTES;   // 196608

__device__ __half g_xh[(size_t)N_DIM * N_DIM];
__device__ __half g_wb[(size_t)N_DIM * N_DIM];

// ---------------------------------------------------------------------------
// prep: binarize W -> fp16, cast x -> fp16
// ---------------------------------------------------------------------------
__global__ void prep_kernel(const float4* __restrict__ x,
                            const float4* __restrict__ W, int n4) {
    int i = blockIdx.x * blockDim.x + threadIdx.x;
    if (i >= n4) return;
    float4 xv = x[i];
    float4 wv = W[i];
    float xs[4] = {xv.x, xv.y, xv.z, xv.w};
    float ws[4] = {wv.x, wv.y, wv.z, wv.w};
    alignas(8) __half xh[4], wb[4];
#pragma unroll
    for (int j = 0; j < 4; j++) {
        xh[j] = __float2half_rn(xs[j]);
        float s = (ws[j] > 0.0f) ? 1.0f : ((ws[j] < 0.0f) ? -1.0f : 0.0f);
        wb[j] = __float2half_rn(s);
    }
    size_t base = (size_t)i * 4;
    *reinterpret_cast<uint2*>(g_xh + base) = *reinterpret_cast<uint2*>(xh);
    *reinterpret_cast<uint2*>(g_wb + base) = *reinterpret_cast<uint2*>(wb);
}

// ---------------------------------------------------------------------------
// PTX helpers
// ---------------------------------------------------------------------------
__device__ __forceinline__ void cp16(uint32_t smem_addr, const void* gmem_ptr) {
    asm volatile("cp.async.cg.shared.global [%0], [%1], 16;\n"
                 :: "r"(smem_addr), "l"(gmem_ptr) : "memory");
}

__device__ __forceinline__ void ldsm_x4(uint32_t* r, uint32_t a) {
    asm volatile("ldmatrix.sync.aligned.m8n8.x4.shared.b16 {%0,%1,%2,%3}, [%4];\n"
                 : "=r"(r[0]), "=r"(r[1]), "=r"(r[2]), "=r"(r[3]) : "r"(a));
}

__device__ __forceinline__ void mma16816(float* d, const uint32_t* a,
                                         const uint32_t* b) {
    asm volatile("mma.sync.aligned.m16n8k16.row.col.f32.f16.f16.f32 "
                 "{%0,%1,%2,%3},{%4,%5,%6,%7},{%8,%9},{%0,%1,%2,%3};\n"
                 : "+f"(d[0]), "+f"(d[1]), "+f"(d[2]), "+f"(d[3])
                 : "r"(a[0]), "r"(a[1]), "r"(a[2]), "r"(a[3]),
                   "r"(b[0]), "r"(b[1]));
}

// ---------------------------------------------------------------------------
// GEMM: 256 threads = 8 warps in 2(M) x 4(N), warp tile 64x64, CTA 128x256.
// Stage: A rows 0-127 (128B/row, XOR swizzle) at 0; B rows 0-255 at +16384.
// Swizzle: off(row, ch16) = row*128 + ((ch16 ^ (row&7)) << 4)
// ---------------------------------------------------------------------------
__global__ void __launch_bounds__(256, 1)
gemm_kernel(const float* __restrict__ bias, float* __restrict__ out) {
    extern __shared__ char smem[];
    const uint32_t smem_base = (uint32_t)__cvta_generic_to_shared(smem);
    const int tid   = threadIdx.x;
    const int lane  = tid & 31;
    const int warp  = tid >> 5;
    const int warpM = warp & 1;      // 0..1
    const int warpN = warp >> 1;     // 0..3
    const int mBase = blockIdx.y * 128;
    const int nBase = blockIdx.x * 256;

    float acc[4][8][4];
#pragma unroll
    for (int a = 0; a < 4; a++)
#pragma unroll
        for (int b = 0; b < 8; b++)
#pragma unroll
            for (int c = 0; c < 4; c++) acc[a][b][c] = 0.0f;

    // ---- cp.async per-thread mapping: ch16 = tid&7, rows rbase + p*32 ----
    const int rbase = tid >> 3;               // 0..31
    const int ch    = tid & 7;
    const uint32_t swz = (uint32_t)rbase * 128 + (uint32_t)((ch ^ (rbase & 7)) << 4);
    const __half* gA = g_xh + (size_t)(mBase + rbase) * N_DIM + ch * 8;
    const __half* gB = g_wb + (size_t)(nBase + rbase) * N_DIM + ch * 8;

    auto prefetch = [&](int kt) {
        const uint32_t sb = smem_base + (uint32_t)(kt & 3) * STAGE_BYTES;
        const int k0 = kt * KTILE;
#pragma unroll
        for (int p = 0; p < 4; p++)           // A: rows rbase+32p (0..127)
            cp16(sb + swz + (uint32_t)p * 4096, gA + (size_t)p * 32 * N_DIM + k0);
#pragma unroll
        for (int p = 0; p < 8; p++)           // B: rows rbase+32p (0..255)
            cp16(sb + 16384 + swz + (uint32_t)p * 4096,
                 gB + (size_t)p * 32 * N_DIM + k0);
        asm volatile("cp.async.commit_group;\n" ::: "memory");
    };

    // ---- ldmatrix per-thread row/offset precompute ----
    const uint32_t la7 = lane & 7;
    const uint32_t aHi = (lane >> 4) & 1;     // k +8 selector for A
    const uint32_t bHi = (lane >> 3) & 1;     // k +8 selector for B
    uint32_t aOff[4], bOff[4];
#pragma unroll
    for (int tm = 0; tm < 4; tm++) {
        uint32_t r = warpM * 64 + tm * 16 + (lane & 15);
        aOff[tm] = r * 128;
    }
#pragma unroll
    for (int pr = 0; pr < 4; pr++) {
        uint32_t r = warpN * 64 + pr * 16 + la7 + ((lane >> 4) & 1) * 8;
        bOff[pr] = 16384 + r * 128;
    }

    uint32_t ah[2][4][4], bq[2][4][4];

    auto loadfrags = [&](uint32_t sb, int ks, int buf) {
        const uint32_t ca = (((uint32_t)ks * 2 + aHi) ^ la7) << 4;
        const uint32_t cb = (((uint32_t)ks * 2 + bHi) ^ la7) << 4;
#pragma unroll
        for (int tm = 0; tm < 4; tm++) ldsm_x4(ah[buf][tm], sb + aOff[tm] + ca);
#pragma unroll
        for (int pr = 0; pr < 4; pr++) ldsm_x4(bq[buf][pr], sb + bOff[pr] + cb);
    };

    auto mmas = [&](int buf) {
#pragma unroll
        for (int tm = 0; tm < 4; tm++)
#pragma unroll
            for (int pr = 0; pr < 4; pr++) {
                mma16816(acc[tm][2 * pr],     ah[buf][tm], &bq[buf][pr][0]);
                mma16816(acc[tm][2 * pr + 1], ah[buf][tm], &bq[buf][pr][2]);
            }
    };

    prefetch(0);
    prefetch(1);
    asm volatile("cp.async.wait_group 0;\n" ::: "memory");
    __syncthreads();
    loadfrags(smem_base, 0, 0);   // (kt=0, ks=0) into buf 0

    // window = 2 ktiles, ONE wait+barrier per window
    for (int kt = 0; kt < NKT; kt += 2) {
        const uint32_t sb0 = smem_base + (uint32_t)(kt & 3) * STAGE_BYTES;
        const uint32_t sb1 = smem_base + (uint32_t)((kt + 1) & 3) * STAGE_BYTES;
        // prefetch next window (stages of kt-2/kt-1; readers done per last barrier)
        if (kt + 2 < NKT) prefetch(kt + 2);
        if (kt + 3 < NKT) prefetch(kt + 3);
        // ---- ktile kt: frags(kt,ks0) already in buf0 ----
#pragma unroll
        for (int ks = 0; ks < 3; ks++) {
            loadfrags(sb0, ks + 1, (ks + 1) & 1);
            mmas(ks & 1);
        }
        loadfrags(sb1, 0, 0);     // kt+1 ks0 (stage data arrived last window)
        mmas(1);                  // kt ks3
        // ---- ktile kt+1 ----
#pragma unroll
        for (int ks = 0; ks < 3; ks++) {
            loadfrags(sb1, ks + 1, (ks + 1) & 1);
            mmas(ks & 1);
        }
        // ks3 of kt+1 in buf1, not yet crunched
        if (kt + 2 < NKT) {
            asm volatile("cp.async.wait_group 0;\n" ::: "memory");
            __syncthreads();      // all smem reads of kt,kt+1 complete above
            loadfrags(smem_base + (uint32_t)((kt + 2) & 3) * STAGE_BYTES, 0, 0);
        }
        mmas(1);                  // kt+1 ks3 — carried across the barrier
    }

    // ---- epilogue: + bias, fp32 store ----
    const int g  = lane >> 2;
    const int t4 = lane & 3;
#pragma unroll
    for (int tm = 0; tm < 4; tm++) {
        int rr = mBase + warpM * 64 + tm * 16 + g;
#pragma unroll
        for (int tn = 0; tn < 8; tn++) {
            int col = nBase + warpN * 64 + tn * 8 + 2 * t4;
            float2 b2 = *reinterpret_cast<const float2*>(bias + col);
            float2 v0, v1;
            v0.x = acc[tm][tn][0] + b2.x;
            v0.y = acc[tm][tn][1] + b2.y;
            v1.x = acc[tm][tn][2] + b2.x;
            v1.y = acc[tm][tn][3] + b2.y;
            *reinterpret_cast<float2*>(out + (size_t)rr * N_DIM + col)       = v0;
            *reinterpret_cast<float2*>(out + (size_t)(rr + 8) * N_DIM + col) = v1;
        }
    }
}

// ---------------------------------------------------------------------------
extern "C" void kernel_launch(void* const* d_in, const int* in_sizes, int n_in,
                              void* d_out, int out_size) {
    const float* x = (const float*)d_in[0];
    const float* W = (const float*)d_in[1];
    const float* b = (const float*)d_in[2];
    float* out = (float*)d_out;

    const int n4 = (N_DIM * N_DIM) / 4;
    prep_kernel<<<(n4 + 255) / 256, 256>>>((const float4*)x, (const float4*)W, n4);

    cudaFuncSetAttribute(gemm_kernel, cudaFuncAttributeMaxDynamicSharedMemorySize,
                         SMEM_BYTES);
    dim3 grid(N_DIM / 256, N_DIM / 128);  // (16, 32) = 512 CTAs
    gemm_kernel<<<grid, 256, SMEM_BYTES>>>(b, out);
}

// round 16
// speedup vs baseline: 1.3288x; 1.1792x over previous
#include <cuda_runtime.h>
#include <cuda_fp16.h>
#include <cstdint>

// out[n,o] = sum_i x[n,i] * sign(W[o,i]) + b[o],  N=IN=OUT=4096, fp32 in/out.
//
// Legacy HMMA f32-acc mma.sync (tcgen05 not emittable at compute_103).
// Round-15 evidence: per-ktile barriers are cheap only when a co-resident CTA
// covers the drain; 1-CTA/SM configs lose. Round-11 structure retained (CTA
// 128x128, 4 warps 64x64, KTILE 64, 3-stage cp.async, barrier-crossing
// fragment carry, 2 CTAs/SM). Round-16 addition: TEMPORAL SKEW — odd-bid CTAs
// delay ~660 cyc (half a ktile) after issuing their first prefetches, breaking
// the phase-lock between co-resident CTAs so their barrier drains interleave.

#define N_DIM 4096
constexpr int KTILE = 64;
constexpr int NKT = N_DIM / KTILE;           // 64
constexpr int STAGE_BYTES = 2 * 128 * 128;   // A 16KB + B 16KB
constexpr int SMEM_BYTES = 3 * STAGE_BYTES;  // 98304

__device__ __half g_xh[(size_t)N_DIM * N_DIM];
__device__ __half g_wb[(size_t)N_DIM * N_DIM];

// ---------------------------------------------------------------------------
// prep: binarize W -> fp16, cast x -> fp16
// ---------------------------------------------------------------------------
__global__ void prep_kernel(const float4* __restrict__ x,
                            const float4* __restrict__ W, int n4) {
    int i = blockIdx.x * blockDim.x + threadIdx.x;
    if (i >= n4) return;
    float4 xv = x[i];
    float4 wv = W[i];
    float xs[4] = {xv.x, xv.y, xv.z, xv.w};
    float ws[4] = {wv.x, wv.y, wv.z, wv.w};
    alignas(8) __half xh[4], wb[4];
#pragma unroll
    for (int j = 0; j < 4; j++) {
        xh[j] = __float2half_rn(xs[j]);
        float s = (ws[j] > 0.0f) ? 1.0f : ((ws[j] < 0.0f) ? -1.0f : 0.0f);
        wb[j] = __float2half_rn(s);
    }
    size_t base = (size_t)i * 4;
    *reinterpret_cast<uint2*>(g_xh + base) = *reinterpret_cast<uint2*>(xh);
    *reinterpret_cast<uint2*>(g_wb + base) = *reinterpret_cast<uint2*>(wb);
}

// ---------------------------------------------------------------------------
// PTX helpers
// ---------------------------------------------------------------------------
__device__ __forceinline__ void cp16(uint32_t smem_addr, const void* gmem_ptr) {
    asm volatile("cp.async.cg.shared.global [%0], [%1], 16;\n"
                 :: "r"(smem_addr), "l"(gmem_ptr) : "memory");
}

__device__ __forceinline__ void ldsm_x4(uint32_t* r, uint32_t a) {
    asm volatile("ldmatrix.sync.aligned.m8n8.x4.shared.b16 {%0,%1,%2,%3}, [%4];\n"
                 : "=r"(r[0]), "=r"(r[1]), "=r"(r[2]), "=r"(r[3]) : "r"(a));
}

__device__ __forceinline__ void mma16816(float* d, const uint32_t* a,
                                         const uint32_t* b) {
    asm volatile("mma.sync.aligned.m16n8k16.row.col.f32.f16.f16.f32 "
                 "{%0,%1,%2,%3},{%4,%5,%6,%7},{%8,%9},{%0,%1,%2,%3};\n"
                 : "+f"(d[0]), "+f"(d[1]), "+f"(d[2]), "+f"(d[3])
                 : "r"(a[0]), "r"(a[1]), "r"(a[2]), "r"(a[3]),
                   "r"(b[0]), "r"(b[1]));
}

// ---------------------------------------------------------------------------
// GEMM: 128 threads = 4 warps in 2(M) x 2(N), warp tile 64x64.
// Stage layout: A rows 0-127 (128B/row XOR-swizzled); B at +16384 same.
// Swizzle: byte_off(row, ch16) = row*128 + ((ch16 ^ (row&7)) << 4)
// ---------------------------------------------------------------------------
__global__ void __launch_bounds__(128, 2)
gemm_kernel(const float* __restrict__ bias, float* __restrict__ out) {
    extern __shared__ char smem[];
    const uint32_t smem_base = (uint32_t)__cvta_generic_to_shared(smem);
    const int tid   = threadIdx.x;
    const int lane  = tid & 31;
    const int warp  = tid >> 5;
    const int warpM = warp & 1;
    const int warpN = warp >> 1;
    const int mBase = blockIdx.y * 128;
    const int nBase = blockIdx.x * 128;

    float acc[4][8][4];
#pragma unroll
    for (int a = 0; a < 4; a++)
#pragma unroll
        for (int b = 0; b < 8; b++)
#pragma unroll
            for (int c = 0; c < 4; c++) acc[a][b][c] = 0.0f;

    // ---- cp.async per-thread mapping: ch16 = tid&7, rows rbase + p*16 ----
    const int rbase = tid >> 3;               // 0..15
    const int ch    = tid & 7;
    const uint32_t swA = (uint32_t)rbase * 128 + (uint32_t)((ch ^ (rbase & 7)) << 4);
    const __half* gA = g_xh + (size_t)(mBase + rbase) * N_DIM + ch * 8;
    const __half* gB = g_wb + (size_t)(nBase + rbase) * N_DIM + ch * 8;

    auto prefetch = [&](int kt) {
        const uint32_t sb = smem_base + (uint32_t)(kt % 3) * STAGE_BYTES;
        const int k0 = kt * KTILE;
#pragma unroll
        for (int p = 0; p < 8; p++) {
            uint32_t so = swA + (uint32_t)p * 2048;      // +16 rows
            size_t go = (size_t)p * 16 * N_DIM + k0;
            cp16(sb + so,         gA + go);
            cp16(sb + 16384 + so, gB + go);
        }
        asm volatile("cp.async.commit_group;\n" ::: "memory");
    };

    // ---- ldmatrix per-thread row/offset precompute ----
    const uint32_t la7 = lane & 7;
    const uint32_t aHi = (lane >> 4) & 1;     // k +8 selector for A
    const uint32_t bHi = (lane >> 3) & 1;     // k +8 selector for B
    uint32_t aOff[4], bOff[4];
#pragma unroll
    for (int tm = 0; tm < 4; tm++) {
        uint32_t r = warpM * 64 + tm * 16 + (lane & 15);
        aOff[tm] = r * 128;
    }
#pragma unroll
    for (int pr = 0; pr < 4; pr++) {
        uint32_t r = warpN * 64 + pr * 16 + la7 + ((lane >> 4) & 1) * 8;
        bOff[pr] = 16384 + r * 128;
    }

    uint32_t ah[2][4][4], bq[2][4][4];

    auto loadfrags = [&](uint32_t sb, int ks, int buf) {
        const uint32_t ca = (((uint32_t)ks * 2 + aHi) ^ la7) << 4;
        const uint32_t cb = (((uint32_t)ks * 2 + bHi) ^ la7) << 4;
#pragma unroll
        for (int tm = 0; tm < 4; tm++) ldsm_x4(ah[buf][tm], sb + aOff[tm] + ca);
#pragma unroll
        for (int pr = 0; pr < 4; pr++) ldsm_x4(bq[buf][pr], sb + bOff[pr] + cb);
    };

    auto mmas = [&](int buf) {
#pragma unroll
        for (int tm = 0; tm < 4; tm++)
#pragma unroll
            for (int pr = 0; pr < 4; pr++) {
                mma16816(acc[tm][2 * pr],     ah[buf][tm], &bq[buf][pr][0]);
                mma16816(acc[tm][2 * pr + 1], ah[buf][tm], &bq[buf][pr][2]);
            }
    };

    prefetch(0);
    prefetch(1);

    // ---- temporal skew: odd CTAs delay ~660 cyc (half a ktile) so that
    // co-resident CTAs' barrier rhythms interleave instead of phase-locking.
    // Loads issued above proceed during the delay. Deterministic FFMA chain.
    if (blockIdx.x & 1) {
        float d = bias[0] + 1.0f;
#pragma unroll 1
        for (int i = 0; i < 165; i++)
            d = fmaf(d, 1.0000001f, 1e-30f);
        asm volatile("" :: "f"(d));   // keep the chain alive
    }

    asm volatile("cp.async.wait_group 1;\n" ::: "memory");
    __syncthreads();
    loadfrags(smem_base, 0, 0);   // (kt=0, ks=0) into buf 0

    for (int kt = 0; kt < NKT; kt++) {
        const uint32_t sb = smem_base + (uint32_t)(kt % 3) * STAGE_BYTES;
#pragma unroll
        for (int ks = 0; ks < 3; ks++) {
            loadfrags(sb, ks + 1, (ks + 1) & 1);
            mmas(ks & 1);
        }
        // ks3 frags in buf 1, not yet crunched
        if (kt + 2 < NKT) prefetch(kt + 2);
        if (kt + 1 < NKT) {
            if (kt + 2 < NKT)
                asm volatile("cp.async.wait_group 1;\n" ::: "memory");
            else
                asm volatile("cp.async.wait_group 0;\n" ::: "memory");
            __syncthreads();
            loadfrags(smem_base + (uint32_t)((kt + 1) % 3) * STAGE_BYTES, 0, 0);
        }
        mmas(1);   // keeps tensor pipe busy through the sync window
    }

    // ---- epilogue: + bias, fp32 store ----
    const int g  = lane >> 2;
    const int t4 = lane & 3;
#pragma unroll
    for (int tm = 0; tm < 4; tm++) {
        int rr = mBase + warpM * 64 + tm * 16 + g;
#pragma unroll
        for (int tn = 0; tn < 8; tn++) {
            int col = nBase + warpN * 64 + tn * 8 + 2 * t4;
            float2 b2 = *reinterpret_cast<const float2*>(bias + col);
            float2 v0, v1;
            v0.x = acc[tm][tn][0] + b2.x;
            v0.y = acc[tm][tn][1] + b2.y;
            v1.x = acc[tm][tn][2] + b2.x;
            v1.y = acc[tm][tn][3] + b2.y;
            *reinterpret_cast<float2*>(out + (size_t)rr * N_DIM + col)       = v0;
            *reinterpret_cast<float2*>(out + (size_t)(rr + 8) * N_DIM + col) = v1;
        }
    }
}

// ---------------------------------------------------------------------------
extern "C" void kernel_launch(void* const* d_in, const int* in_sizes, int n_in,
                              void* d_out, int out_size) {
    const float* x = (const float*)d_in[0];
    const float* W = (const float*)d_in[1];
    const float* b = (const float*)d_in[2];
    float* out = (float*)d_out;

    const int n4 = (N_DIM * N_DIM) / 4;
    prep_kernel<<<(n4 + 255) / 256, 256>>>((const float4*)x, (const float4*)W, n4);

    cudaFuncSetAttribute(gemm_kernel, cudaFuncAttributeMaxDynamicSharedMemorySize,
                         SMEM_BYTES);
    dim3 grid(N_DIM / 128, N_DIM / 128);  // (32, 32)
    gemm_kernel<<<grid, 128, SMEM_BYTES>>>(b, out);
}

// round 17
// speedup vs baseline: 1.3310x; 1.0017x over previous
#include <cuda_runtime.h>
#include <cuda_fp16.h>
#include <cstdint>

// out[n,o] = sum_i x[n,i] * sign(W[o,i]) + b[o],  N=IN=OUT=4096, fp32 in/out.
//
// Legacy HMMA f32-acc mma.sync (tcgen05 not emittable at compute_103).
// GEMM locked at the round-11 plateau (tensor 82%, 275us): CTA 128x128,
// 4 warps 64x64, KTILE 64, 3-stage cp.async, XOR swizzle, 2 CTAs/SM,
// barrier-crossing fragment carry. Round-17: prep kernel widened to 2 float4
// per thread per array (16B stores, 2x MLP); dead skew code removed.

#define N_DIM 4096
constexpr int KTILE = 64;
constexpr int NKT = N_DIM / KTILE;           // 64
constexpr int STAGE_BYTES = 2 * 128 * 128;   // A 16KB + B 16KB
constexpr int SMEM_BYTES = 3 * STAGE_BYTES;  // 98304

__device__ __half g_xh[(size_t)N_DIM * N_DIM];
__device__ __half g_wb[(size_t)N_DIM * N_DIM];

// ---------------------------------------------------------------------------
// prep: binarize W -> fp16, cast x -> fp16. 8 elements (2 float4) per thread,
// 16B stores, independent loads for MLP.
// ---------------------------------------------------------------------------
__global__ void prep_kernel(const float4* __restrict__ x,
                            const float4* __restrict__ W, int n8) {
    int i = blockIdx.x * blockDim.x + threadIdx.x;
    if (i >= n8) return;
    float4 xv0 = x[2 * i];
    float4 xv1 = x[2 * i + 1];
    float4 wv0 = W[2 * i];
    float4 wv1 = W[2 * i + 1];
    float xs[8] = {xv0.x, xv0.y, xv0.z, xv0.w, xv1.x, xv1.y, xv1.z, xv1.w};
    float ws[8] = {wv0.x, wv0.y, wv0.z, wv0.w, wv1.x, wv1.y, wv1.z, wv1.w};
    alignas(16) __half xh[8], wb[8];
#pragma unroll
    for (int j = 0; j < 8; j++) {
        xh[j] = __float2half_rn(xs[j]);
        float s = (ws[j] > 0.0f) ? 1.0f : ((ws[j] < 0.0f) ? -1.0f : 0.0f);
        wb[j] = __float2half_rn(s);
    }
    size_t base = (size_t)i * 8;
    *reinterpret_cast<uint4*>(g_xh + base) = *reinterpret_cast<const uint4*>(xh);
    *reinterpret_cast<uint4*>(g_wb + base) = *reinterpret_cast<const uint4*>(wb);
}

// ---------------------------------------------------------------------------
// PTX helpers
// ---------------------------------------------------------------------------
__device__ __forceinline__ void cp16(uint32_t smem_addr, const void* gmem_ptr) {
    asm volatile("cp.async.cg.shared.global [%0], [%1], 16;\n"
                 :: "r"(smem_addr), "l"(gmem_ptr) : "memory");
}

__device__ __forceinline__ void ldsm_x4(uint32_t* r, uint32_t a) {
    asm volatile("ldmatrix.sync.aligned.m8n8.x4.shared.b16 {%0,%1,%2,%3}, [%4];\n"
                 : "=r"(r[0]), "=r"(r[1]), "=r"(r[2]), "=r"(r[3]) : "r"(a));
}

__device__ __forceinline__ void mma16816(float* d, const uint32_t* a,
                                         const uint32_t* b) {
    asm volatile("mma.sync.aligned.m16n8k16.row.col.f32.f16.f16.f32 "
                 "{%0,%1,%2,%3},{%4,%5,%6,%7},{%8,%9},{%0,%1,%2,%3};\n"
                 : "+f"(d[0]), "+f"(d[1]), "+f"(d[2]), "+f"(d[3])
                 : "r"(a[0]), "r"(a[1]), "r"(a[2]), "r"(a[3]),
                   "r"(b[0]), "r"(b[1]));
}

// ---------------------------------------------------------------------------
// GEMM: 128 threads = 4 warps in 2(M) x 2(N), warp tile 64x64.
// Stage layout: A rows 0-127 (128B/row XOR-swizzled); B at +16384 same.
// Swizzle: byte_off(row, ch16) = row*128 + ((ch16 ^ (row&7)) << 4)
// ---------------------------------------------------------------------------
__global__ void __launch_bounds__(128, 2)
gemm_kernel(const float* __restrict__ bias, float* __restrict__ out) {
    extern __shared__ char smem[];
    const uint32_t smem_base = (uint32_t)__cvta_generic_to_shared(smem);
    const int tid   = threadIdx.x;
    const int lane  = tid & 31;
    const int warp  = tid >> 5;
    const int warpM = warp & 1;
    const int warpN = warp >> 1;
    const int mBase = blockIdx.y * 128;
    const int nBase = blockIdx.x * 128;

    float acc[4][8][4];
#pragma unroll
    for (int a = 0; a < 4; a++)
#pragma unroll
        for (int b = 0; b < 8; b++)
#pragma unroll
            for (int c = 0; c < 4; c++) acc[a][b][c] = 0.0f;

    // ---- cp.async per-thread mapping: ch16 = tid&7, rows rbase + p*16 ----
    const int rbase = tid >> 3;               // 0..15
    const int ch    = tid & 7;
    const uint32_t swA = (uint32_t)rbase * 128 + (uint32_t)((ch ^ (rbase & 7)) << 4);
    const __half* gA = g_xh + (size_t)(mBase + rbase) * N_DIM + ch * 8;
    const __half* gB = g_wb + (size_t)(nBase + rbase) * N_DIM + ch * 8;

    auto prefetch = [&](int kt) {
        const uint32_t sb = smem_base + (uint32_t)(kt % 3) * STAGE_BYTES;
        const int k0 = kt * KTILE;
#pragma unroll
        for (int p = 0; p < 8; p++) {
            uint32_t so = swA + (uint32_t)p * 2048;      // +16 rows
            size_t go = (size_t)p * 16 * N_DIM + k0;
            cp16(sb + so,         gA + go);
            cp16(sb + 16384 + so, gB + go);
        }
        asm volatile("cp.async.commit_group;\n" ::: "memory");
    };

    // ---- ldmatrix per-thread row/offset precompute ----
    const uint32_t la7 = lane & 7;
    const uint32_t aHi = (lane >> 4) & 1;     // k +8 selector for A
    const uint32_t bHi = (lane >> 3) & 1;     // k +8 selector for B
    uint32_t aOff[4], bOff[4];
#pragma unroll
    for (int tm = 0; tm < 4; tm++) {
        uint32_t r = warpM * 64 + tm * 16 + (lane & 15);
        aOff[tm] = r * 128;
    }
#pragma unroll
    for (int pr = 0; pr < 4; pr++) {
        uint32_t r = warpN * 64 + pr * 16 + la7 + ((lane >> 4) & 1) * 8;
        bOff[pr] = 16384 + r * 128;
    }

    uint32_t ah[2][4][4], bq[2][4][4];

    auto loadfrags = [&](uint32_t sb, int ks, int buf) {
        const uint32_t ca = (((uint32_t)ks * 2 + aHi) ^ la7) << 4;
        const uint32_t cb = (((uint32_t)ks * 2 + bHi) ^ la7) << 4;
#pragma unroll
        for (int tm = 0; tm < 4; tm++) ldsm_x4(ah[buf][tm], sb + aOff[tm] + ca);
#pragma unroll
        for (int pr = 0; pr < 4; pr++) ldsm_x4(bq[buf][pr], sb + bOff[pr] + cb);
    };

    auto mmas = [&](int buf) {
#pragma unroll
        for (int tm = 0; tm < 4; tm++)
#pragma unroll
            for (int pr = 0; pr < 4; pr++) {
                mma16816(acc[tm][2 * pr],     ah[buf][tm], &bq[buf][pr][0]);
                mma16816(acc[tm][2 * pr + 1], ah[buf][tm], &bq[buf][pr][2]);
            }
    };

    prefetch(0);
    prefetch(1);
    asm volatile("cp.async.wait_group 1;\n" ::: "memory");
    __syncthreads();
    loadfrags(smem_base, 0, 0);   // (kt=0, ks=0) into buf 0

    for (int kt = 0; kt < NKT; kt++) {
        const uint32_t sb = smem_base + (uint32_t)(kt % 3) * STAGE_BYTES;
#pragma unroll
        for (int ks = 0; ks < 3; ks++) {
            loadfrags(sb, ks + 1, (ks + 1) & 1);
            mmas(ks & 1);
        }
        // ks3 frags in buf 1, not yet crunched
        if (kt + 2 < NKT) prefetch(kt + 2);
        if (kt + 1 < NKT) {
            if (kt + 2 < NKT)
                asm volatile("cp.async.wait_group 1;\n" ::: "memory");
            else
                asm volatile("cp.async.wait_group 0;\n" ::: "memory");
            __syncthreads();
            loadfrags(smem_base + (uint32_t)((kt + 1) % 3) * STAGE_BYTES, 0, 0);
        }
        mmas(1);   // keeps tensor pipe busy through the sync window
    }

    // ---- epilogue: + bias, fp32 store ----
    const int g  = lane >> 2;
    const int t4 = lane & 3;
#pragma unroll
    for (int tm = 0; tm < 4; tm++) {
        int rr = mBase + warpM * 64 + tm * 16 + g;
#pragma unroll
        for (int tn = 0; tn < 8; tn++) {
            int col = nBase + warpN * 64 + tn * 8 + 2 * t4;
            float2 b2 = *reinterpret_cast<const float2*>(bias + col);
            float2 v0, v1;
            v0.x = acc[tm][tn][0] + b2.x;
            v0.y = acc[tm][tn][1] + b2.y;
            v1.x = acc[tm][tn][2] + b2.x;
            v1.y = acc[tm][tn][3] + b2.y;
            *reinterpret_cast<float2*>(out + (size_t)rr * N_DIM + col)       = v0;
            *reinterpret_cast<float2*>(out + (size_t)(rr + 8) * N_DIM + col) = v1;
        }
    }
}

// ---------------------------------------------------------------------------
extern "C" void kernel_launch(void* const* d_in, const int* in_sizes, int n_in,
                              void* d_out, int out_size) {
    const float* x = (const float*)d_in[0];
    const float* W = (const float*)d_in[1];
    const float* b = (const float*)d_in[2];
    float* out = (float*)d_out;

    const int n8 = (N_DIM * N_DIM) / 8;
    prep_kernel<<<(n8 + 255) / 256, 256>>>((const float4*)x, (const float4*)W, n8);

    cudaFuncSetAttribute(gemm_kernel, cudaFuncAttributeMaxDynamicSharedMemorySize,
                         SMEM_BYTES);
    dim3 grid(N_DIM / 128, N_DIM / 128);  // (32, 32)
    gemm_kernel<<<grid, 128, SMEM_BYTES>>>(b, out);
}